// round 12
// baseline (speedup 1.0000x reference)
#include <cuda_runtime.h>
#include <cuda_bf16.h>
#include <cstdint>

#define NN 50000   // nodes
#define MM 10000   // hyperedges
#define DD 128     // feature dim

// ---------------- static scratch ----------------
__device__ float g_esum [MM * DD];   // hyperedge sums      5.1 MB
__device__ float g_eproj[MM * DD];   // emean @ Wveu        5.1 MB
__device__ float g_wvu  [DD * DD];   // W_v @ W_u_top
__device__ float g_wveu [DD * DD];   // W_v @ W_e @ W_u_bot
__device__ int   g_ecnt [MM];
__device__ int   g_ncnt [NN];
__device__ int   g_colmin = 0x7fffffff;   // idempotent across replays

// ---------------- col min ----------------
__global__ void k_colmin(const int* __restrict__ col, int E) {
    int v = 0x7fffffff;
    for (int j = blockIdx.x * blockDim.x + threadIdx.x; j < E;
         j += gridDim.x * blockDim.x)
        v = min(v, __ldg(&col[j]));
#pragma unroll
    for (int o = 16; o > 0; o >>= 1) v = min(v, __shfl_down_sync(0xffffffffu, v, o));
    if ((threadIdx.x & 31) == 0) atomicMin(&g_colmin, v);
}

// ---------------- degree histograms (both directions) ----------------
__global__ void k_hist(const int* __restrict__ row, const int* __restrict__ col, int E) {
    const int cmin = g_colmin;
    const int tid = blockIdx.x * blockDim.x + threadIdx.x;
    const int stride = gridDim.x * blockDim.x;
    for (int e = tid; e < E; e += 2 * stride) {
        int e2 = e + stride;
        int c0 = __ldg(&col[e]) - cmin;
        int r0 = __ldg(&row[e]);
        if (e2 < E) {
            int c1 = __ldg(&col[e2]) - cmin;
            int r1 = __ldg(&row[e2]);
            atomicAdd(&g_ecnt[c0], 1);
            atomicAdd(&g_ecnt[c1], 1);
            atomicAdd(&g_ncnt[r0], 1);
            atomicAdd(&g_ncnt[r1], 1);
        } else {
            atomicAdd(&g_ecnt[c0], 1);
            atomicAdd(&g_ncnt[r0], 1);
        }
    }
}

// ---------------- weight combos: Wvu = Wv@Wu_top ; Wveu = Wv@We@Wu_bot ----------------
__global__ void __launch_bounds__(128) k_combo(
    const float* __restrict__ Wv, const float* __restrict__ We,
    const float* __restrict__ Wu)
{
    __shared__ float rowv[DD];
    __shared__ float tmp[DD];
    const int c = threadIdx.x;
    const int b = blockIdx.x;
    const float* Wu_top = Wu;
    const float* Wu_bot = Wu + DD * DD;

    if (b < DD) {
        const int r = b;
        rowv[c] = Wv[r * DD + c];
        __syncthreads();
        float a0 = 0.f, a1 = 0.f;
#pragma unroll
        for (int k = 0; k < DD; k += 2) {
            a0 = fmaf(rowv[k],     Wu_top[(k)     * DD + c], a0);
            a1 = fmaf(rowv[k + 1], Wu_top[(k + 1) * DD + c], a1);
        }
        g_wvu[r * DD + c] = a0 + a1;
    } else {
        const int r = b - DD;
        rowv[c] = Wv[r * DD + c];
        __syncthreads();
        float a0 = 0.f, a1 = 0.f;
#pragma unroll
        for (int k = 0; k < DD; k += 2) {
            a0 = fmaf(rowv[k],     We[(k)     * DD + c], a0);
            a1 = fmaf(rowv[k + 1], We[(k + 1) * DD + c], a1);
        }
        tmp[c] = a0 + a1;
        __syncthreads();
        float b0 = 0.f, b1 = 0.f;
#pragma unroll
        for (int k = 0; k < DD; k += 2) {
            b0 = fmaf(tmp[k],     Wu_bot[(k)     * DD + c], b0);
            b1 = fmaf(tmp[k + 1], Wu_bot[(k + 1) * DD + c], b1);
        }
        g_wveu[r * DD + c] = b0 + b1;
    }
}

// ---------------- vector float atomic add / L2-only load ----------------
__device__ __forceinline__ void red_add_v4(float* p, float4 v) {
    asm volatile("red.global.add.v4.f32 [%0], {%1,%2,%3,%4};"
                 :: "l"(p), "f"(v.x), "f"(v.y), "f"(v.z), "f"(v.w) : "memory");
}
__device__ __forceinline__ float4 ldcg_v4(const float* p) {
    float4 v;
    asm volatile("ld.global.cg.v4.f32 {%0,%1,%2,%3}, [%4];"
                 : "=f"(v.x), "=f"(v.y), "=f"(v.z), "=f"(v.w) : "l"(p));
    return v;
}

// ---------------- scatter 1: raw node features -> hyperedge sums ----------------
__global__ void k_scatter1(const float* __restrict__ x,
                           const int* __restrict__ row, const int* __restrict__ col, int E) {
    const int cmin = g_colmin;
    const int lane = threadIdx.x & 31;
    const int warp = (blockIdx.x * blockDim.x + threadIdx.x) >> 5;
    const int nw   = (gridDim.x * blockDim.x) >> 5;
    for (int e = warp; e < E; e += 2 * nw) {
        int e2 = e + nw;
        int r0 = __ldg(&row[e]);
        int c0 = __ldg(&col[e]) - cmin;
        float4 v0 = ldcg_v4(&x[(size_t)r0 * DD + lane * 4]);
        if (e2 < E) {
            int r1 = __ldg(&row[e2]);
            int c1 = __ldg(&col[e2]) - cmin;
            float4 v1 = ldcg_v4(&x[(size_t)r1 * DD + lane * 4]);
            red_add_v4(&g_esum[(size_t)c0 * DD + lane * 4], v0);
            red_add_v4(&g_esum[(size_t)c1 * DD + lane * 4], v1);
        } else {
            red_add_v4(&g_esum[(size_t)c0 * DD + lane * 4], v0);
        }
    }
}

// ---------------- scatter 2: scaled eproj rows -> out (GEMM REDs there too) ----------------
__global__ void k_scatter2(const int* __restrict__ row, const int* __restrict__ col,
                           float* __restrict__ out, int E) {
    const int cmin = g_colmin;
    const int lane = threadIdx.x & 31;
    const int warp = (blockIdx.x * blockDim.x + threadIdx.x) >> 5;
    const int nw   = (gridDim.x * blockDim.x) >> 5;
    for (int e = warp; e < E; e += 2 * nw) {
        int e2 = e + nw;
        int r0 = __ldg(&row[e]);
        int c0 = __ldg(&col[e]) - cmin;
        float s0 = 1.0f / fmaxf((float)__ldg(&g_ncnt[r0]), 1.0f);
        float4 v0 = ldcg_v4(&g_eproj[(size_t)c0 * DD + lane * 4]);
        v0.x *= s0; v0.y *= s0; v0.z *= s0; v0.w *= s0;
        if (e2 < E) {
            int r1 = __ldg(&row[e2]);
            int c1 = __ldg(&col[e2]) - cmin;
            float s1 = 1.0f / fmaxf((float)__ldg(&g_ncnt[r1]), 1.0f);
            float4 v1 = ldcg_v4(&g_eproj[(size_t)c1 * DD + lane * 4]);
            v1.x *= s1; v1.y *= s1; v1.z *= s1; v1.w *= s1;
            red_add_v4(&out[(size_t)r0 * DD + lane * 4], v0);
            red_add_v4(&out[(size_t)r1 * DD + lane * 4], v1);
        } else {
            red_add_v4(&out[(size_t)r0 * DD + lane * 4], v0);
        }
    }
}

// ---------------- packed f32x2 FMA helpers ----------------
__device__ __forceinline__ unsigned long long pack_dup(float a) {
    unsigned long long r;
    uint32_t u = __float_as_uint(a);
    asm("mov.b64 %0, {%1, %1};" : "=l"(r) : "r"(u));
    return r;
}
__device__ __forceinline__ void fma_x2(unsigned long long& acc,
                                       unsigned long long a, unsigned long long b) {
    asm("fma.rn.f32x2 %0, %1, %2, %0;" : "+l"(acc) : "l"(a), "l"(b));
}
__device__ __forceinline__ float2 unpack_x2(unsigned long long v) {
    float2 r;
    uint32_t lo, hi;
    asm("mov.b64 {%0, %1}, %2;" : "=r"(lo), "=r"(hi) : "l"(v));
    r.x = __uint_as_float(lo);
    r.y = __uint_as_float(hi);
    return r;
}

// ---------------- double-buffered SGEMM body (f32x2 inner loop) ----------------
// SCALE: A rows scaled by 1/max(cnt[row],1)
// BIAS:  add bias to result
// REDOUT: accumulate into C via red.add (C pre-zeroed) instead of store
template <bool SCALE, bool BIAS, bool REDOUT>
__device__ __forceinline__ void gemm_body(
    const float* __restrict__ A0, const int* __restrict__ cnt0,
    const float* __restrict__ Bm, const float* __restrict__ bias,
    float* __restrict__ C, int Mrows)
{
    __shared__ float As[2][16][132];
    __shared__ __align__(16) float Bs[2][16][128];

    const int tid = threadIdx.x;
    const int ty = tid >> 4;
    const int tx = tid & 15;
    const int rowBase = blockIdx.x * 128;

    const int aRow = tid >> 2;
    const int aCol = (tid & 3) << 2;
    const int bRow = tid >> 5;
    const int bCol = (tid & 31) << 2;

    float scl[2] = {1.0f, 1.0f};
    if (SCALE) {
#pragma unroll
        for (int p = 0; p < 2; p++) {
            int gr = rowBase + aRow + p * 64;
            if (gr < Mrows) scl[p] = 1.0f / fmaxf((float)__ldg(&cnt0[gr]), 1.0f);
        }
    }

    unsigned long long acc2[8][4];
#pragma unroll
    for (int i = 0; i < 8; i++)
#pragma unroll
        for (int j = 0; j < 4; j++) acc2[i][j] = 0ull;

    float4 pa[2], pb[2];
#pragma unroll
    for (int p = 0; p < 2; p++) {
        int gr = rowBase + aRow + p * 64;
        pa[p] = make_float4(0.f, 0.f, 0.f, 0.f);
        if (gr < Mrows) {
            pa[p] = *(const float4*)&A0[(size_t)gr * DD + aCol];
            if (SCALE) { pa[p].x *= scl[p]; pa[p].y *= scl[p]; pa[p].z *= scl[p]; pa[p].w *= scl[p]; }
        }
        pb[p] = *(const float4*)&Bm[(size_t)(bRow + p * 8) * DD + bCol];
    }
#pragma unroll
    for (int p = 0; p < 2; p++) {
        int r = aRow + p * 64;
        As[0][aCol + 0][r] = pa[p].x;
        As[0][aCol + 1][r] = pa[p].y;
        As[0][aCol + 2][r] = pa[p].z;
        As[0][aCol + 3][r] = pa[p].w;
        *(float4*)&Bs[0][bRow + p * 8][bCol] = pb[p];
    }
    __syncthreads();

#pragma unroll
    for (int kb = 0; kb < 8; kb++) {
        if (kb < 7) {
            const int ko = (kb + 1) * 16;
#pragma unroll
            for (int p = 0; p < 2; p++) {
                int gr = rowBase + aRow + p * 64;
                pa[p] = make_float4(0.f, 0.f, 0.f, 0.f);
                if (gr < Mrows) {
                    pa[p] = *(const float4*)&A0[(size_t)gr * DD + ko + aCol];
                    if (SCALE) { pa[p].x *= scl[p]; pa[p].y *= scl[p]; pa[p].z *= scl[p]; pa[p].w *= scl[p]; }
                }
                pb[p] = *(const float4*)&Bm[(size_t)(ko + bRow + p * 8) * DD + bCol];
            }
        }
        const int cb = kb & 1;
#pragma unroll
        for (int k = 0; k < 16; k++) {
            float ar[8];
            *(float4*)&ar[0] = *(const float4*)&As[cb][k][ty * 8];
            *(float4*)&ar[4] = *(const float4*)&As[cb][k][ty * 8 + 4];
            const unsigned long long* bp =
                (const unsigned long long*)&Bs[cb][k][tx * 8];
            unsigned long long br2[4];
            br2[0] = bp[0]; br2[1] = bp[1]; br2[2] = bp[2]; br2[3] = bp[3];
#pragma unroll
            for (int i = 0; i < 8; i++) {
                unsigned long long ai = pack_dup(ar[i]);
#pragma unroll
                for (int j = 0; j < 4; j++) fma_x2(acc2[i][j], ai, br2[j]);
            }
        }
        if (kb < 7) {
            const int nb = cb ^ 1;
#pragma unroll
            for (int p = 0; p < 2; p++) {
                int r = aRow + p * 64;
                As[nb][aCol + 0][r] = pa[p].x;
                As[nb][aCol + 1][r] = pa[p].y;
                As[nb][aCol + 2][r] = pa[p].z;
                As[nb][aCol + 3][r] = pa[p].w;
                *(float4*)&Bs[nb][bRow + p * 8][bCol] = pb[p];
            }
            __syncthreads();
        }
    }

#pragma unroll
    for (int i = 0; i < 8; i++) {
        int gr = rowBase + ty * 8 + i;
        if (gr >= Mrows) continue;
#pragma unroll
        for (int j = 0; j < 4; j += 2) {
            float2 v0 = unpack_x2(acc2[i][j]);
            float2 v1 = unpack_x2(acc2[i][j + 1]);
            float4 v = make_float4(v0.x, v0.y, v1.x, v1.y);
            int gc = tx * 8 + j * 2;
            if (BIAS) {
                v.x += __ldg(&bias[gc + 0]);
                v.y += __ldg(&bias[gc + 1]);
                v.z += __ldg(&bias[gc + 2]);
                v.w += __ldg(&bias[gc + 3]);
            }
            if (REDOUT) red_add_v4(&C[(size_t)gr * DD + gc], v);
            else        *(float4*)&C[(size_t)gr * DD + gc] = v;
        }
    }
}

// side GEMM: out += x@Wvu + bias   (out pre-zeroed; commutes with scatter2)
__global__ void __launch_bounds__(256, 2) k_gemm_bias_red(
    const float* A, const float* B, const float* bias, float* C, int Mrows)
{
    gemm_body<false, true, true>(A, nullptr, B, bias, C, Mrows);
}

// eproj = (esum/ecnt) @ Wveu
__global__ void __launch_bounds__(256, 2) k_gemm_scale(
    const float* A, const int* cnt, const float* B, float* C, int Mrows)
{
    gemm_body<true, false, false>(A, cnt, B, nullptr, C, Mrows);
}

// ---------------- in-place relu ----------------
__global__ void k_relu(float* __restrict__ out, int N) {
    int total = N * (DD / 4);
    for (int i = blockIdx.x * blockDim.x + threadIdx.x; i < total;
         i += gridDim.x * blockDim.x) {
        float4 v = *(const float4*)&out[(size_t)i * 4];
        v.x = fmaxf(v.x, 0.0f);
        v.y = fmaxf(v.y, 0.0f);
        v.z = fmaxf(v.z, 0.0f);
        v.w = fmaxf(v.w, 0.0f);
        *(float4*)&out[(size_t)i * 4] = v;
    }
}

// ---------------- launch ----------------
extern "C" void kernel_launch(void* const* d_in, const int* in_sizes, int n_in,
                              void* d_out, int out_size)
{
    const float* x   = (const float*)d_in[0];
    const int*   ei  = (const int*)  d_in[1];
    const float* Wv  = (const float*)d_in[2];
    const float* We  = (const float*)d_in[3];
    const float* Wu  = (const float*)d_in[4];
    const float* bu  = (const float*)d_in[5];
    float* out = (float*)d_out;

    const int E = in_sizes[1] / 2;
    const int N = in_sizes[0] / DD;
    const int* rowp = ei;
    const int* colp = ei + E;

    float* esum;  cudaGetSymbolAddress((void**)&esum,  g_esum);
    float* eproj; cudaGetSymbolAddress((void**)&eproj, g_eproj);
    float* wvu;   cudaGetSymbolAddress((void**)&wvu,   g_wvu);
    float* wveu;  cudaGetSymbolAddress((void**)&wveu,  g_wveu);
    int* ecnt;    cudaGetSymbolAddress((void**)&ecnt,  g_ecnt);
    int* ncnt;    cudaGetSymbolAddress((void**)&ncnt,  g_ncnt);

    cudaStream_t side1, side2;
    cudaStreamCreateWithFlags(&side1, cudaStreamNonBlocking);
    cudaStreamCreateWithFlags(&side2, cudaStreamNonBlocking);
    cudaEvent_t evEntry, evZero, evColmin, evGemm, evHist;
    cudaEventCreateWithFlags(&evEntry,  cudaEventDisableTiming);
    cudaEventCreateWithFlags(&evZero,   cudaEventDisableTiming);
    cudaEventCreateWithFlags(&evColmin, cudaEventDisableTiming);
    cudaEventCreateWithFlags(&evGemm,   cudaEventDisableTiming);
    cudaEventCreateWithFlags(&evHist,   cudaEventDisableTiming);

    cudaEventRecord(evEntry, 0);

    // side2: zero all accumulators + out via memset nodes
    cudaStreamWaitEvent(side2, evEntry, 0);
    cudaMemsetAsync(esum, 0, (size_t)MM * DD * sizeof(float), side2);
    cudaMemsetAsync(ecnt, 0, (size_t)MM * sizeof(int), side2);
    cudaMemsetAsync(ncnt, 0, (size_t)NN * sizeof(int), side2);
    cudaMemsetAsync(out,  0, (size_t)out_size * sizeof(float), side2);
    cudaEventRecord(evZero, side2);

    // main: colmin
    k_colmin<<<1024, 256>>>(colp, E);
    cudaEventRecord(evColmin, 0);

    // side1: combo -> GEMM (REDs into zeroed out); joins only before relu
    cudaStreamWaitEvent(side1, evEntry, 0);
    k_combo<<<256, 128, 0, side1>>>(Wv, We, Wu);
    cudaStreamWaitEvent(side1, evZero, 0);
    k_gemm_bias_red<<<(N + 127) / 128, 256, 0, side1>>>(x, wvu, bu, out, N);
    cudaEventRecord(evGemm, side1);

    // side2: hist (needs colmin + zeroed counters), overlaps scatter1
    cudaStreamWaitEvent(side2, evColmin, 0);
    k_hist<<<2048, 256, 0, side2>>>(rowp, colp, E);
    cudaEventRecord(evHist, side2);

    // main: scatter1 (needs colmin in-stream + zeroed esum)
    cudaStreamWaitEvent(0, evZero, 0);
    k_scatter1<<<3072, 256>>>(x, rowp, colp, E);
    cudaStreamWaitEvent(0, evHist, 0);
    k_gemm_scale<<<(MM + 127) / 128, 256>>>(esum, ecnt, wveu, eproj, MM);
    // scatter2 needs eproj + ncnt (joined) + zeroed out (joined) — NOT the GEMM
    k_scatter2<<<3072, 256>>>(rowp, colp, out, E);

    // join GEMM, then relu in place
    cudaStreamWaitEvent(0, evGemm, 0);
    k_relu<<<2048, 256>>>(out, N);

    cudaEventDestroy(evEntry);
    cudaEventDestroy(evZero);
    cudaEventDestroy(evColmin);
    cudaEventDestroy(evGemm);
    cudaEventDestroy(evHist);
    cudaStreamDestroy(side1);
    cudaStreamDestroy(side2);
}

// round 13
// speedup vs baseline: 1.0463x; 1.0463x over previous
#include <cuda_runtime.h>
#include <cuda_bf16.h>
#include <cstdint>

#define NN 50000   // nodes
#define MM 10000   // hyperedges
#define DD 128     // feature dim

// ---------------- static scratch ----------------
__device__ float g_esum [MM * DD];   // hyperedge sums      5.1 MB
__device__ float g_eproj[MM * DD];   // emean @ Wveu        5.1 MB
__device__ float g_wvu  [DD * DD];   // W_v @ W_u_top
__device__ float g_wveu [DD * DD];   // W_v @ W_e @ W_u_bot
__device__ int   g_ecnt [MM];
__device__ int   g_ncnt [NN];
__device__ int   g_colmin = 0x7fffffff;   // idempotent across replays

// ---------------- init: zero esum + counts, colmin ----------------
__global__ void k_init(const int* __restrict__ col, int E) {
    int i = blockIdx.x * blockDim.x + threadIdx.x;
    int stride = gridDim.x * blockDim.x;
    float4 z = make_float4(0.f, 0.f, 0.f, 0.f);
    for (int j = i; j < MM * DD / 4; j += stride) ((float4*)g_esum)[j] = z;
    for (int j = i; j < NN; j += stride) g_ncnt[j] = 0;
    for (int j = i; j < MM; j += stride) g_ecnt[j] = 0;
    int v = 0x7fffffff;
    for (int j = i; j < E; j += stride) v = min(v, __ldg(&col[j]));
#pragma unroll
    for (int o = 16; o > 0; o >>= 1) v = min(v, __shfl_down_sync(0xffffffffu, v, o));
    if ((threadIdx.x & 31) == 0) atomicMin(&g_colmin, v);
}

// ---------------- degree histograms (both directions) ----------------
__global__ void k_hist(const int* __restrict__ row, const int* __restrict__ col, int E) {
    const int cmin = g_colmin;
    const int tid = blockIdx.x * blockDim.x + threadIdx.x;
    const int stride = gridDim.x * blockDim.x;
    for (int e = tid; e < E; e += 2 * stride) {
        int e2 = e + stride;
        int c0 = __ldg(&col[e]) - cmin;
        int r0 = __ldg(&row[e]);
        if (e2 < E) {
            int c1 = __ldg(&col[e2]) - cmin;
            int r1 = __ldg(&row[e2]);
            atomicAdd(&g_ecnt[c0], 1);
            atomicAdd(&g_ecnt[c1], 1);
            atomicAdd(&g_ncnt[r0], 1);
            atomicAdd(&g_ncnt[r1], 1);
        } else {
            atomicAdd(&g_ecnt[c0], 1);
            atomicAdd(&g_ncnt[r0], 1);
        }
    }
}

// ---------------- weight combos: Wvu = Wv@Wu_top ; Wveu = Wv@We@Wu_bot ----------------
__global__ void __launch_bounds__(128) k_combo(
    const float* __restrict__ Wv, const float* __restrict__ We,
    const float* __restrict__ Wu)
{
    __shared__ float rowv[DD];
    __shared__ float tmp[DD];
    const int c = threadIdx.x;
    const int b = blockIdx.x;
    const float* Wu_top = Wu;
    const float* Wu_bot = Wu + DD * DD;

    if (b < DD) {
        const int r = b;
        rowv[c] = Wv[r * DD + c];
        __syncthreads();
        float a0 = 0.f, a1 = 0.f;
#pragma unroll
        for (int k = 0; k < DD; k += 2) {
            a0 = fmaf(rowv[k],     Wu_top[(k)     * DD + c], a0);
            a1 = fmaf(rowv[k + 1], Wu_top[(k + 1) * DD + c], a1);
        }
        g_wvu[r * DD + c] = a0 + a1;
    } else {
        const int r = b - DD;
        rowv[c] = Wv[r * DD + c];
        __syncthreads();
        float a0 = 0.f, a1 = 0.f;
#pragma unroll
        for (int k = 0; k < DD; k += 2) {
            a0 = fmaf(rowv[k],     We[(k)     * DD + c], a0);
            a1 = fmaf(rowv[k + 1], We[(k + 1) * DD + c], a1);
        }
        tmp[c] = a0 + a1;
        __syncthreads();
        float b0 = 0.f, b1 = 0.f;
#pragma unroll
        for (int k = 0; k < DD; k += 2) {
            b0 = fmaf(tmp[k],     Wu_bot[(k)     * DD + c], b0);
            b1 = fmaf(tmp[k + 1], Wu_bot[(k + 1) * DD + c], b1);
        }
        g_wveu[r * DD + c] = b0 + b1;
    }
}

// ---------------- vector float atomic add / L2-only load ----------------
__device__ __forceinline__ void red_add_v4(float* p, float4 v) {
    asm volatile("red.global.add.v4.f32 [%0], {%1,%2,%3,%4};"
                 :: "l"(p), "f"(v.x), "f"(v.y), "f"(v.z), "f"(v.w) : "memory");
}
__device__ __forceinline__ float4 ldcg_v4(const float* p) {
    float4 v;
    asm volatile("ld.global.cg.v4.f32 {%0,%1,%2,%3}, [%4];"
                 : "=f"(v.x), "=f"(v.y), "=f"(v.z), "=f"(v.w) : "l"(p));
    return v;
}

// ---------------- scatter 1: raw node features -> hyperedge sums (4-way MLP) ----------------
__global__ void k_scatter1(const float* __restrict__ x,
                           const int* __restrict__ row, const int* __restrict__ col, int E) {
    const int cmin = g_colmin;
    const int lane = threadIdx.x & 31;
    const int warp = (blockIdx.x * blockDim.x + threadIdx.x) >> 5;
    const int nw   = (gridDim.x * blockDim.x) >> 5;
    int e = warp;
    for (; e + 3 * nw < E; e += 4 * nw) {
        int r0 = __ldg(&row[e]);
        int r1 = __ldg(&row[e + nw]);
        int r2 = __ldg(&row[e + 2 * nw]);
        int r3 = __ldg(&row[e + 3 * nw]);
        int c0 = __ldg(&col[e]) - cmin;
        int c1 = __ldg(&col[e + nw]) - cmin;
        int c2 = __ldg(&col[e + 2 * nw]) - cmin;
        int c3 = __ldg(&col[e + 3 * nw]) - cmin;
        float4 v0 = ldcg_v4(&x[(size_t)r0 * DD + lane * 4]);
        float4 v1 = ldcg_v4(&x[(size_t)r1 * DD + lane * 4]);
        float4 v2 = ldcg_v4(&x[(size_t)r2 * DD + lane * 4]);
        float4 v3 = ldcg_v4(&x[(size_t)r3 * DD + lane * 4]);
        red_add_v4(&g_esum[(size_t)c0 * DD + lane * 4], v0);
        red_add_v4(&g_esum[(size_t)c1 * DD + lane * 4], v1);
        red_add_v4(&g_esum[(size_t)c2 * DD + lane * 4], v2);
        red_add_v4(&g_esum[(size_t)c3 * DD + lane * 4], v3);
    }
    for (; e < E; e += nw) {
        int r0 = __ldg(&row[e]);
        int c0 = __ldg(&col[e]) - cmin;
        float4 v0 = ldcg_v4(&x[(size_t)r0 * DD + lane * 4]);
        red_add_v4(&g_esum[(size_t)c0 * DD + lane * 4], v0);
    }
}

// ---------------- scatter 2: scaled eproj rows -> out (bias already there, 4-way) ----------------
__global__ void k_scatter2(const int* __restrict__ row, const int* __restrict__ col,
                           float* __restrict__ out, int E) {
    const int cmin = g_colmin;
    const int lane = threadIdx.x & 31;
    const int warp = (blockIdx.x * blockDim.x + threadIdx.x) >> 5;
    const int nw   = (gridDim.x * blockDim.x) >> 5;
    int e = warp;
    for (; e + 3 * nw < E; e += 4 * nw) {
        int r0 = __ldg(&row[e]);
        int r1 = __ldg(&row[e + nw]);
        int r2 = __ldg(&row[e + 2 * nw]);
        int r3 = __ldg(&row[e + 3 * nw]);
        int c0 = __ldg(&col[e]) - cmin;
        int c1 = __ldg(&col[e + nw]) - cmin;
        int c2 = __ldg(&col[e + 2 * nw]) - cmin;
        int c3 = __ldg(&col[e + 3 * nw]) - cmin;
        float s0 = 1.0f / fmaxf((float)__ldg(&g_ncnt[r0]), 1.0f);
        float s1 = 1.0f / fmaxf((float)__ldg(&g_ncnt[r1]), 1.0f);
        float s2 = 1.0f / fmaxf((float)__ldg(&g_ncnt[r2]), 1.0f);
        float s3 = 1.0f / fmaxf((float)__ldg(&g_ncnt[r3]), 1.0f);
        float4 v0 = ldcg_v4(&g_eproj[(size_t)c0 * DD + lane * 4]);
        float4 v1 = ldcg_v4(&g_eproj[(size_t)c1 * DD + lane * 4]);
        float4 v2 = ldcg_v4(&g_eproj[(size_t)c2 * DD + lane * 4]);
        float4 v3 = ldcg_v4(&g_eproj[(size_t)c3 * DD + lane * 4]);
        v0.x *= s0; v0.y *= s0; v0.z *= s0; v0.w *= s0;
        v1.x *= s1; v1.y *= s1; v1.z *= s1; v1.w *= s1;
        v2.x *= s2; v2.y *= s2; v2.z *= s2; v2.w *= s2;
        v3.x *= s3; v3.y *= s3; v3.z *= s3; v3.w *= s3;
        red_add_v4(&out[(size_t)r0 * DD + lane * 4], v0);
        red_add_v4(&out[(size_t)r1 * DD + lane * 4], v1);
        red_add_v4(&out[(size_t)r2 * DD + lane * 4], v2);
        red_add_v4(&out[(size_t)r3 * DD + lane * 4], v3);
    }
    for (; e < E; e += nw) {
        int r0 = __ldg(&row[e]);
        int c0 = __ldg(&col[e]) - cmin;
        float s0 = 1.0f / fmaxf((float)__ldg(&g_ncnt[r0]), 1.0f);
        float4 v0 = ldcg_v4(&g_eproj[(size_t)c0 * DD + lane * 4]);
        v0.x *= s0; v0.y *= s0; v0.z *= s0; v0.w *= s0;
        red_add_v4(&out[(size_t)r0 * DD + lane * 4], v0);
    }
}

// ---------------- packed f32x2 FMA helpers ----------------
__device__ __forceinline__ unsigned long long pack_dup(float a) {
    unsigned long long r;
    uint32_t u = __float_as_uint(a);
    asm("mov.b64 %0, {%1, %1};" : "=l"(r) : "r"(u));
    return r;
}
__device__ __forceinline__ void fma_x2(unsigned long long& acc,
                                       unsigned long long a, unsigned long long b) {
    asm("fma.rn.f32x2 %0, %1, %2, %0;" : "+l"(acc) : "l"(a), "l"(b));
}
__device__ __forceinline__ float2 unpack_x2(unsigned long long v) {
    float2 r;
    uint32_t lo, hi;
    asm("mov.b64 {%0, %1}, %2;" : "=r"(lo), "=r"(hi) : "l"(v));
    r.x = __uint_as_float(lo);
    r.y = __uint_as_float(hi);
    return r;
}

// ---------------- double-buffered SGEMM body (f32x2 inner loop) ----------------
template <bool SCALE, bool BIAS>
__device__ __forceinline__ void gemm_body(
    const float* __restrict__ A0, const int* __restrict__ cnt0,
    const float* __restrict__ Bm, const float* __restrict__ bias,
    float* __restrict__ C, int Mrows)
{
    __shared__ float As[2][16][132];
    __shared__ __align__(16) float Bs[2][16][128];

    const int tid = threadIdx.x;
    const int ty = tid >> 4;
    const int tx = tid & 15;
    const int rowBase = blockIdx.x * 128;

    const int aRow = tid >> 2;
    const int aCol = (tid & 3) << 2;
    const int bRow = tid >> 5;
    const int bCol = (tid & 31) << 2;

    float scl[2] = {1.0f, 1.0f};
    if (SCALE) {
#pragma unroll
        for (int p = 0; p < 2; p++) {
            int gr = rowBase + aRow + p * 64;
            if (gr < Mrows) scl[p] = 1.0f / fmaxf((float)__ldg(&cnt0[gr]), 1.0f);
        }
    }

    unsigned long long acc2[8][4];
#pragma unroll
    for (int i = 0; i < 8; i++)
#pragma unroll
        for (int j = 0; j < 4; j++) acc2[i][j] = 0ull;

    float4 pa[2], pb[2];
#pragma unroll
    for (int p = 0; p < 2; p++) {
        int gr = rowBase + aRow + p * 64;
        pa[p] = make_float4(0.f, 0.f, 0.f, 0.f);
        if (gr < Mrows) {
            pa[p] = *(const float4*)&A0[(size_t)gr * DD + aCol];
            if (SCALE) { pa[p].x *= scl[p]; pa[p].y *= scl[p]; pa[p].z *= scl[p]; pa[p].w *= scl[p]; }
        }
        pb[p] = *(const float4*)&Bm[(size_t)(bRow + p * 8) * DD + bCol];
    }
#pragma unroll
    for (int p = 0; p < 2; p++) {
        int r = aRow + p * 64;
        As[0][aCol + 0][r] = pa[p].x;
        As[0][aCol + 1][r] = pa[p].y;
        As[0][aCol + 2][r] = pa[p].z;
        As[0][aCol + 3][r] = pa[p].w;
        *(float4*)&Bs[0][bRow + p * 8][bCol] = pb[p];
    }
    __syncthreads();

#pragma unroll
    for (int kb = 0; kb < 8; kb++) {
        if (kb < 7) {
            const int ko = (kb + 1) * 16;
#pragma unroll
            for (int p = 0; p < 2; p++) {
                int gr = rowBase + aRow + p * 64;
                pa[p] = make_float4(0.f, 0.f, 0.f, 0.f);
                if (gr < Mrows) {
                    pa[p] = *(const float4*)&A0[(size_t)gr * DD + ko + aCol];
                    if (SCALE) { pa[p].x *= scl[p]; pa[p].y *= scl[p]; pa[p].z *= scl[p]; pa[p].w *= scl[p]; }
                }
                pb[p] = *(const float4*)&Bm[(size_t)(ko + bRow + p * 8) * DD + bCol];
            }
        }
        const int cb = kb & 1;
#pragma unroll
        for (int k = 0; k < 16; k++) {
            float ar[8];
            *(float4*)&ar[0] = *(const float4*)&As[cb][k][ty * 8];
            *(float4*)&ar[4] = *(const float4*)&As[cb][k][ty * 8 + 4];
            const unsigned long long* bp =
                (const unsigned long long*)&Bs[cb][k][tx * 8];
            unsigned long long br2[4];
            br2[0] = bp[0]; br2[1] = bp[1]; br2[2] = bp[2]; br2[3] = bp[3];
#pragma unroll
            for (int i = 0; i < 8; i++) {
                unsigned long long ai = pack_dup(ar[i]);
#pragma unroll
                for (int j = 0; j < 4; j++) fma_x2(acc2[i][j], ai, br2[j]);
            }
        }
        if (kb < 7) {
            const int nb = cb ^ 1;
#pragma unroll
            for (int p = 0; p < 2; p++) {
                int r = aRow + p * 64;
                As[nb][aCol + 0][r] = pa[p].x;
                As[nb][aCol + 1][r] = pa[p].y;
                As[nb][aCol + 2][r] = pa[p].z;
                As[nb][aCol + 3][r] = pa[p].w;
                *(float4*)&Bs[nb][bRow + p * 8][bCol] = pb[p];
            }
            __syncthreads();
        }
    }

#pragma unroll
    for (int i = 0; i < 8; i++) {
        int gr = rowBase + ty * 8 + i;
        if (gr >= Mrows) continue;
#pragma unroll
        for (int j = 0; j < 4; j += 2) {
            float2 v0 = unpack_x2(acc2[i][j]);
            float2 v1 = unpack_x2(acc2[i][j + 1]);
            float4 v = make_float4(v0.x, v0.y, v1.x, v1.y);
            int gc = tx * 8 + j * 2;
            if (BIAS) {
                v.x += __ldg(&bias[gc + 0]);
                v.y += __ldg(&bias[gc + 1]);
                v.z += __ldg(&bias[gc + 2]);
                v.w += __ldg(&bias[gc + 3]);
            }
            *(float4*)&C[(size_t)gr * DD + gc] = v;
        }
    }
}

__global__ void __launch_bounds__(256, 2) k_gemm_bias(
    const float* A, const float* B, const float* bias, float* C, int Mrows)
{
    gemm_body<false, true>(A, nullptr, B, bias, C, Mrows);
}

__global__ void __launch_bounds__(256, 2) k_gemm_scale(
    const float* A, const int* cnt, const float* B, float* C, int Mrows)
{
    gemm_body<true, false>(A, cnt, B, nullptr, C, Mrows);
}

// ---------------- in-place relu ----------------
__global__ void k_relu(float* __restrict__ out, int N) {
    int total = N * (DD / 4);
    for (int i = blockIdx.x * blockDim.x + threadIdx.x; i < total;
         i += gridDim.x * blockDim.x) {
        float4 v = *(const float4*)&out[(size_t)i * 4];
        v.x = fmaxf(v.x, 0.0f);
        v.y = fmaxf(v.y, 0.0f);
        v.z = fmaxf(v.z, 0.0f);
        v.w = fmaxf(v.w, 0.0f);
        *(float4*)&out[(size_t)i * 4] = v;
    }
}

// ---------------- launch ----------------
extern "C" void kernel_launch(void* const* d_in, const int* in_sizes, int n_in,
                              void* d_out, int out_size)
{
    const float* x   = (const float*)d_in[0];
    const int*   ei  = (const int*)  d_in[1];
    const float* Wv  = (const float*)d_in[2];
    const float* We  = (const float*)d_in[3];
    const float* Wu  = (const float*)d_in[4];
    const float* bu  = (const float*)d_in[5];
    float* out = (float*)d_out;

    const int E = in_sizes[1] / 2;
    const int N = in_sizes[0] / DD;
    const int* rowp = ei;
    const int* colp = ei + E;

    float* esum;  cudaGetSymbolAddress((void**)&esum,  g_esum);
    float* eproj; cudaGetSymbolAddress((void**)&eproj, g_eproj);
    float* wvu;   cudaGetSymbolAddress((void**)&wvu,   g_wvu);
    float* wveu;  cudaGetSymbolAddress((void**)&wveu,  g_wveu);
    int* ecnt;    cudaGetSymbolAddress((void**)&ecnt,  g_ecnt);

    cudaStream_t side1, side2;
    cudaStreamCreateWithFlags(&side1, cudaStreamNonBlocking);
    cudaStreamCreateWithFlags(&side2, cudaStreamNonBlocking);
    cudaEvent_t evEntry, evInit, evGemm, evHist;
    cudaEventCreateWithFlags(&evEntry, cudaEventDisableTiming);
    cudaEventCreateWithFlags(&evInit,  cudaEventDisableTiming);
    cudaEventCreateWithFlags(&evGemm,  cudaEventDisableTiming);
    cudaEventCreateWithFlags(&evHist,  cudaEventDisableTiming);

    // side1 (forks at entry): combo -> out = x@Wvu + bias (plain stores)
    cudaEventRecord(evEntry, 0);
    cudaStreamWaitEvent(side1, evEntry, 0);
    k_combo<<<256, 128, 0, side1>>>(Wv, We, Wu);
    k_gemm_bias<<<(N + 127) / 128, 256, 0, side1>>>(x, wvu, bu, out, N);
    cudaEventRecord(evGemm, side1);

    // main: init (zero + colmin)
    k_init<<<512, 256>>>(colp, E);
    cudaEventRecord(evInit, 0);

    // side2 (forks after init): hist, overlapped with scatter1
    cudaStreamWaitEvent(side2, evInit, 0);
    k_hist<<<2048, 256, 0, side2>>>(rowp, colp, E);
    cudaEventRecord(evHist, side2);

    // main: scatter1, then (after hist) gemm_scale
    k_scatter1<<<4096, 256>>>(x, rowp, colp, E);
    cudaStreamWaitEvent(0, evHist, 0);
    k_gemm_scale<<<(MM + 127) / 128, 256>>>(esum, ecnt, wveu, eproj, MM);

    // join side GEMM, scatter pre-scaled contributions into out, relu in place
    cudaStreamWaitEvent(0, evGemm, 0);
    k_scatter2<<<4096, 256>>>(rowp, colp, out, E);
    k_relu<<<2048, 256>>>(out, N);

    cudaEventDestroy(evEntry);
    cudaEventDestroy(evInit);
    cudaEventDestroy(evGemm);
    cudaEventDestroy(evHist);
    cudaStreamDestroy(side1);
    cudaStreamDestroy(side2);
}

// round 14
// speedup vs baseline: 1.2272x; 1.1729x over previous
#include <cuda_runtime.h>
#include <cuda_bf16.h>
#include <cstdint>

#define NN 50000   // nodes
#define MM 10000   // hyperedges
#define EE 500000  // incidence pairs (max)
#define DD 128     // feature dim

// ---------------- static scratch ----------------
__device__ float g_esum [MM * DD];   // hyperedge sums      5.1 MB
__device__ float g_eproj[MM * DD];   // emean @ Wveu        5.1 MB
__device__ float g_wvu  [DD * DD];   // W_v @ W_u_top
__device__ float g_wveu [DD * DD];   // W_v @ W_e @ W_u_bot
__device__ int   g_ecnt [MM];
__device__ int   g_ncnt [NN];
__device__ int   g_nofs [NN];        // node CSR segment start
__device__ int   g_ncur [NN];        // placement cursors
__device__ int   g_ncsr [EE];        // hyperedge ids grouped (unordered) by node
__device__ int   g_ntot;             // global offset counter
__device__ int   g_colmin = 0x7fffffff;   // idempotent across replays

// ---------------- init: zero esum + counters, colmin ----------------
__global__ void k_init(const int* __restrict__ col, int E) {
    int i = blockIdx.x * blockDim.x + threadIdx.x;
    int stride = gridDim.x * blockDim.x;
    float4 z = make_float4(0.f, 0.f, 0.f, 0.f);
    for (int j = i; j < MM * DD / 4; j += stride) ((float4*)g_esum)[j] = z;
    for (int j = i; j < NN; j += stride) g_ncnt[j] = 0;
    for (int j = i; j < MM; j += stride) g_ecnt[j] = 0;
    if (i == 0) g_ntot = 0;
    int v = 0x7fffffff;
    for (int j = i; j < E; j += stride) v = min(v, __ldg(&col[j]));
#pragma unroll
    for (int o = 16; o > 0; o >>= 1) v = min(v, __shfl_down_sync(0xffffffffu, v, o));
    if ((threadIdx.x & 31) == 0) atomicMin(&g_colmin, v);
}

// ---------------- degree histograms (both directions) ----------------
__global__ void k_hist(const int* __restrict__ row, const int* __restrict__ col, int E) {
    const int cmin = g_colmin;
    const int tid = blockIdx.x * blockDim.x + threadIdx.x;
    const int stride = gridDim.x * blockDim.x;
    for (int e = tid; e < E; e += 2 * stride) {
        int e2 = e + stride;
        int c0 = __ldg(&col[e]) - cmin;
        int r0 = __ldg(&row[e]);
        if (e2 < E) {
            int c1 = __ldg(&col[e2]) - cmin;
            int r1 = __ldg(&row[e2]);
            atomicAdd(&g_ecnt[c0], 1);
            atomicAdd(&g_ecnt[c1], 1);
            atomicAdd(&g_ncnt[r0], 1);
            atomicAdd(&g_ncnt[r1], 1);
        } else {
            atomicAdd(&g_ecnt[c0], 1);
            atomicAdd(&g_ncnt[r0], 1);
        }
    }
}

// ---------------- scan-free segment offsets (warp-aggregated) ----------------
__global__ void k_offsets() {
    int i = blockIdx.x * blockDim.x + threadIdx.x;
    int lane = threadIdx.x & 31;
    int cnt = (i < NN) ? g_ncnt[i] : 0;
    int s = cnt;
#pragma unroll
    for (int o = 1; o < 32; o <<= 1) {
        int t = __shfl_up_sync(0xffffffffu, s, o);
        if (lane >= o) s += t;
    }
    int warpTotal = __shfl_sync(0xffffffffu, s, 31);
    int base = 0;
    if (lane == 31) base = atomicAdd(&g_ntot, warpTotal);
    base = __shfl_sync(0xffffffffu, base, 31);
    if (i < NN) {
        int beg = base + s - cnt;
        g_nofs[i] = beg;
        g_ncur[i] = beg;
    }
}

// ---------------- CSR placement (node side) ----------------
__global__ void k_place_n(const int* __restrict__ row, const int* __restrict__ col, int E) {
    const int cmin = g_colmin;
    const int tid = blockIdx.x * blockDim.x + threadIdx.x;
    const int stride = gridDim.x * blockDim.x;
    for (int e = tid; e < E; e += stride) {
        int r = __ldg(&row[e]);
        int c = __ldg(&col[e]) - cmin;
        int p = atomicAdd(&g_ncur[r], 1);
        g_ncsr[p] = c;
    }
}

// ---------------- weight combos: Wvu = Wv@Wu_top ; Wveu = Wv@We@Wu_bot ----------------
__global__ void __launch_bounds__(128) k_combo(
    const float* __restrict__ Wv, const float* __restrict__ We,
    const float* __restrict__ Wu)
{
    __shared__ float rowv[DD];
    __shared__ float tmp[DD];
    const int c = threadIdx.x;
    const int b = blockIdx.x;
    const float* Wu_top = Wu;
    const float* Wu_bot = Wu + DD * DD;

    if (b < DD) {
        const int r = b;
        rowv[c] = Wv[r * DD + c];
        __syncthreads();
        float a0 = 0.f, a1 = 0.f;
#pragma unroll
        for (int k = 0; k < DD; k += 2) {
            a0 = fmaf(rowv[k],     Wu_top[(k)     * DD + c], a0);
            a1 = fmaf(rowv[k + 1], Wu_top[(k + 1) * DD + c], a1);
        }
        g_wvu[r * DD + c] = a0 + a1;
    } else {
        const int r = b - DD;
        rowv[c] = Wv[r * DD + c];
        __syncthreads();
        float a0 = 0.f, a1 = 0.f;
#pragma unroll
        for (int k = 0; k < DD; k += 2) {
            a0 = fmaf(rowv[k],     We[(k)     * DD + c], a0);
            a1 = fmaf(rowv[k + 1], We[(k + 1) * DD + c], a1);
        }
        tmp[c] = a0 + a1;
        __syncthreads();
        float b0 = 0.f, b1 = 0.f;
#pragma unroll
        for (int k = 0; k < DD; k += 2) {
            b0 = fmaf(tmp[k],     Wu_bot[(k)     * DD + c], b0);
            b1 = fmaf(tmp[k + 1], Wu_bot[(k + 1) * DD + c], b1);
        }
        g_wveu[r * DD + c] = b0 + b1;
    }
}

// ---------------- vector float atomic add / L2-only load ----------------
__device__ __forceinline__ void red_add_v4(float* p, float4 v) {
    asm volatile("red.global.add.v4.f32 [%0], {%1,%2,%3,%4};"
                 :: "l"(p), "f"(v.x), "f"(v.y), "f"(v.z), "f"(v.w) : "memory");
}
__device__ __forceinline__ float4 ldcg_v4(const float* p) {
    float4 v;
    asm volatile("ld.global.cg.v4.f32 {%0,%1,%2,%3}, [%4];"
                 : "=f"(v.x), "=f"(v.y), "=f"(v.z), "=f"(v.w) : "l"(p));
    return v;
}

// ---------------- scatter 1: raw node features -> hyperedge sums (2-way, R11) ----------------
__global__ void k_scatter1(const float* __restrict__ x,
                           const int* __restrict__ row, const int* __restrict__ col, int E) {
    const int cmin = g_colmin;
    const int lane = threadIdx.x & 31;
    const int warp = (blockIdx.x * blockDim.x + threadIdx.x) >> 5;
    const int nw   = (gridDim.x * blockDim.x) >> 5;
    for (int e = warp; e < E; e += 2 * nw) {
        int e2 = e + nw;
        int r0 = __ldg(&row[e]);
        int c0 = __ldg(&col[e]) - cmin;
        float4 v0 = ldcg_v4(&x[(size_t)r0 * DD + lane * 4]);
        if (e2 < E) {
            int r1 = __ldg(&row[e2]);
            int c1 = __ldg(&col[e2]) - cmin;
            float4 v1 = ldcg_v4(&x[(size_t)r1 * DD + lane * 4]);
            red_add_v4(&g_esum[(size_t)c0 * DD + lane * 4], v0);
            red_add_v4(&g_esum[(size_t)c1 * DD + lane * 4], v1);
        } else {
            red_add_v4(&g_esum[(size_t)c0 * DD + lane * 4], v0);
        }
    }
}

// ---------------- gather_n: per-node mean of eproj + fused relu epilogue ----------------
// out[r] = relu(out[r] + (sum_{c in ncsr[r]} eproj[c]) / max(cnt,1))
__global__ void k_gather_n(float* __restrict__ out, int N) {
    const int lane = threadIdx.x & 31;
    const int seg = (blockIdx.x * blockDim.x + threadIdx.x) >> 5;
    if (seg >= N) return;
    const int beg = g_nofs[seg];
    const int cnt = g_ncnt[seg];
    const int end = beg + cnt;
    float4 acc = make_float4(0.f, 0.f, 0.f, 0.f);
    int i = beg;
    for (; i + 1 < end; i += 2) {
        int c0 = __ldg(&g_ncsr[i]);
        int c1 = __ldg(&g_ncsr[i + 1]);
        float4 v0 = ldcg_v4(&g_eproj[(size_t)c0 * DD + lane * 4]);
        float4 v1 = ldcg_v4(&g_eproj[(size_t)c1 * DD + lane * 4]);
        acc.x += v0.x + v1.x; acc.y += v0.y + v1.y;
        acc.z += v0.z + v1.z; acc.w += v0.w + v1.w;
    }
    if (i < end) {
        int c0 = __ldg(&g_ncsr[i]);
        float4 v0 = ldcg_v4(&g_eproj[(size_t)c0 * DD + lane * 4]);
        acc.x += v0.x; acc.y += v0.y; acc.z += v0.z; acc.w += v0.w;
    }
    float inv = 1.0f / fmaxf((float)cnt, 1.0f);
    float4 o = *(const float4*)&out[(size_t)seg * DD + lane * 4];
    o.x = fmaxf(fmaf(acc.x, inv, o.x), 0.0f);
    o.y = fmaxf(fmaf(acc.y, inv, o.y), 0.0f);
    o.z = fmaxf(fmaf(acc.z, inv, o.z), 0.0f);
    o.w = fmaxf(fmaf(acc.w, inv, o.w), 0.0f);
    *(float4*)&out[(size_t)seg * DD + lane * 4] = o;
}

// ---------------- packed f32x2 FMA helpers ----------------
__device__ __forceinline__ unsigned long long pack_dup(float a) {
    unsigned long long r;
    uint32_t u = __float_as_uint(a);
    asm("mov.b64 %0, {%1, %1};" : "=l"(r) : "r"(u));
    return r;
}
__device__ __forceinline__ void fma_x2(unsigned long long& acc,
                                       unsigned long long a, unsigned long long b) {
    asm("fma.rn.f32x2 %0, %1, %2, %0;" : "+l"(acc) : "l"(a), "l"(b));
}
__device__ __forceinline__ float2 unpack_x2(unsigned long long v) {
    float2 r;
    uint32_t lo, hi;
    asm("mov.b64 {%0, %1}, %2;" : "=r"(lo), "=r"(hi) : "l"(v));
    r.x = __uint_as_float(lo);
    r.y = __uint_as_float(hi);
    return r;
}

// ---------------- double-buffered SGEMM body (f32x2 inner loop) ----------------
template <bool SCALE, bool BIAS>
__device__ __forceinline__ void gemm_body(
    const float* __restrict__ A0, const int* __restrict__ cnt0,
    const float* __restrict__ Bm, const float* __restrict__ bias,
    float* __restrict__ C, int Mrows)
{
    __shared__ float As[2][16][132];
    __shared__ __align__(16) float Bs[2][16][128];

    const int tid = threadIdx.x;
    const int ty = tid >> 4;
    const int tx = tid & 15;
    const int rowBase = blockIdx.x * 128;

    const int aRow = tid >> 2;
    const int aCol = (tid & 3) << 2;
    const int bRow = tid >> 5;
    const int bCol = (tid & 31) << 2;

    float scl[2] = {1.0f, 1.0f};
    if (SCALE) {
#pragma unroll
        for (int p = 0; p < 2; p++) {
            int gr = rowBase + aRow + p * 64;
            if (gr < Mrows) scl[p] = 1.0f / fmaxf((float)__ldg(&cnt0[gr]), 1.0f);
        }
    }

    unsigned long long acc2[8][4];
#pragma unroll
    for (int i = 0; i < 8; i++)
#pragma unroll
        for (int j = 0; j < 4; j++) acc2[i][j] = 0ull;

    float4 pa[2], pb[2];
#pragma unroll
    for (int p = 0; p < 2; p++) {
        int gr = rowBase + aRow + p * 64;
        pa[p] = make_float4(0.f, 0.f, 0.f, 0.f);
        if (gr < Mrows) {
            pa[p] = *(const float4*)&A0[(size_t)gr * DD + aCol];
            if (SCALE) { pa[p].x *= scl[p]; pa[p].y *= scl[p]; pa[p].z *= scl[p]; pa[p].w *= scl[p]; }
        }
        pb[p] = *(const float4*)&Bm[(size_t)(bRow + p * 8) * DD + bCol];
    }
#pragma unroll
    for (int p = 0; p < 2; p++) {
        int r = aRow + p * 64;
        As[0][aCol + 0][r] = pa[p].x;
        As[0][aCol + 1][r] = pa[p].y;
        As[0][aCol + 2][r] = pa[p].z;
        As[0][aCol + 3][r] = pa[p].w;
        *(float4*)&Bs[0][bRow + p * 8][bCol] = pb[p];
    }
    __syncthreads();

#pragma unroll
    for (int kb = 0; kb < 8; kb++) {
        if (kb < 7) {
            const int ko = (kb + 1) * 16;
#pragma unroll
            for (int p = 0; p < 2; p++) {
                int gr = rowBase + aRow + p * 64;
                pa[p] = make_float4(0.f, 0.f, 0.f, 0.f);
                if (gr < Mrows) {
                    pa[p] = *(const float4*)&A0[(size_t)gr * DD + ko + aCol];
                    if (SCALE) { pa[p].x *= scl[p]; pa[p].y *= scl[p]; pa[p].z *= scl[p]; pa[p].w *= scl[p]; }
                }
                pb[p] = *(const float4*)&Bm[(size_t)(ko + bRow + p * 8) * DD + bCol];
            }
        }
        const int cb = kb & 1;
#pragma unroll
        for (int k = 0; k < 16; k++) {
            float ar[8];
            *(float4*)&ar[0] = *(const float4*)&As[cb][k][ty * 8];
            *(float4*)&ar[4] = *(const float4*)&As[cb][k][ty * 8 + 4];
            const unsigned long long* bp =
                (const unsigned long long*)&Bs[cb][k][tx * 8];
            unsigned long long br2[4];
            br2[0] = bp[0]; br2[1] = bp[1]; br2[2] = bp[2]; br2[3] = bp[3];
#pragma unroll
            for (int i = 0; i < 8; i++) {
                unsigned long long ai = pack_dup(ar[i]);
#pragma unroll
                for (int j = 0; j < 4; j++) fma_x2(acc2[i][j], ai, br2[j]);
            }
        }
        if (kb < 7) {
            const int nb = cb ^ 1;
#pragma unroll
            for (int p = 0; p < 2; p++) {
                int r = aRow + p * 64;
                As[nb][aCol + 0][r] = pa[p].x;
                As[nb][aCol + 1][r] = pa[p].y;
                As[nb][aCol + 2][r] = pa[p].z;
                As[nb][aCol + 3][r] = pa[p].w;
                *(float4*)&Bs[nb][bRow + p * 8][bCol] = pb[p];
            }
            __syncthreads();
        }
    }

#pragma unroll
    for (int i = 0; i < 8; i++) {
        int gr = rowBase + ty * 8 + i;
        if (gr >= Mrows) continue;
#pragma unroll
        for (int j = 0; j < 4; j += 2) {
            float2 v0 = unpack_x2(acc2[i][j]);
            float2 v1 = unpack_x2(acc2[i][j + 1]);
            float4 v = make_float4(v0.x, v0.y, v1.x, v1.y);
            int gc = tx * 8 + j * 2;
            if (BIAS) {
                v.x += __ldg(&bias[gc + 0]);
                v.y += __ldg(&bias[gc + 1]);
                v.z += __ldg(&bias[gc + 2]);
                v.w += __ldg(&bias[gc + 3]);
            }
            *(float4*)&C[(size_t)gr * DD + gc] = v;
        }
    }
}

__global__ void __launch_bounds__(256, 2) k_gemm_bias(
    const float* A, const float* B, const float* bias, float* C, int Mrows)
{
    gemm_body<false, true>(A, nullptr, B, bias, C, Mrows);
}

__global__ void __launch_bounds__(256, 2) k_gemm_scale(
    const float* A, const int* cnt, const float* B, float* C, int Mrows)
{
    gemm_body<true, false>(A, cnt, B, nullptr, C, Mrows);
}

// ---------------- launch ----------------
extern "C" void kernel_launch(void* const* d_in, const int* in_sizes, int n_in,
                              void* d_out, int out_size)
{
    const float* x   = (const float*)d_in[0];
    const int*   ei  = (const int*)  d_in[1];
    const float* Wv  = (const float*)d_in[2];
    const float* We  = (const float*)d_in[3];
    const float* Wu  = (const float*)d_in[4];
    const float* bu  = (const float*)d_in[5];
    float* out = (float*)d_out;

    const int E = in_sizes[1] / 2;
    const int N = in_sizes[0] / DD;
    const int* rowp = ei;
    const int* colp = ei + E;

    float* esum;  cudaGetSymbolAddress((void**)&esum,  g_esum);
    float* eproj; cudaGetSymbolAddress((void**)&eproj, g_eproj);
    float* wvu;   cudaGetSymbolAddress((void**)&wvu,   g_wvu);
    float* wveu;  cudaGetSymbolAddress((void**)&wveu,  g_wveu);
    int* ecnt;    cudaGetSymbolAddress((void**)&ecnt,  g_ecnt);

    cudaStream_t side1, side2;
    cudaStreamCreateWithFlags(&side1, cudaStreamNonBlocking);
    cudaStreamCreateWithFlags(&side2, cudaStreamNonBlocking);
    cudaEvent_t evEntry, evInit, evGemm, evCsr;
    cudaEventCreateWithFlags(&evEntry, cudaEventDisableTiming);
    cudaEventCreateWithFlags(&evInit,  cudaEventDisableTiming);
    cudaEventCreateWithFlags(&evGemm,  cudaEventDisableTiming);
    cudaEventCreateWithFlags(&evCsr,   cudaEventDisableTiming);

    // side1 (forks at entry): combo -> out = x@Wvu + bias (plain stores)
    cudaEventRecord(evEntry, 0);
    cudaStreamWaitEvent(side1, evEntry, 0);
    k_combo<<<256, 128, 0, side1>>>(Wv, We, Wu);
    k_gemm_bias<<<(N + 127) / 128, 256, 0, side1>>>(x, wvu, bu, out, N);
    cudaEventRecord(evGemm, side1);

    // main: init (zero + colmin)
    k_init<<<512, 256>>>(colp, E);
    cudaEventRecord(evInit, 0);

    // side2 (forks after init): hist -> offsets -> place (node CSR build),
    // all overlapped with scatter1 on the main stream
    cudaStreamWaitEvent(side2, evInit, 0);
    k_hist<<<2048, 256, 0, side2>>>(rowp, colp, E);
    k_offsets<<<(NN + 255) / 256, 256, 0, side2>>>();
    k_place_n<<<1024, 256, 0, side2>>>(rowp, colp, E);
    cudaEventRecord(evCsr, side2);

    // main: scatter1, then (after CSR/hist) gemm_scale
    k_scatter1<<<4096, 256>>>(x, rowp, colp, E);
    cudaStreamWaitEvent(0, evCsr, 0);
    k_gemm_scale<<<(MM + 127) / 128, 256>>>(esum, ecnt, wveu, eproj, MM);

    // join side GEMM, then fused gather + relu epilogue
    cudaStreamWaitEvent(0, evGemm, 0);
    k_gather_n<<<(N * 32 + 255) / 256, 256>>>(out, N);

    cudaEventDestroy(evEntry);
    cudaEventDestroy(evInit);
    cudaEventDestroy(evGemm);
    cudaEventDestroy(evCsr);
    cudaStreamDestroy(side1);
    cudaStreamDestroy(side2);
}

// round 15
// speedup vs baseline: 1.4946x; 1.2178x over previous
#include <cuda_runtime.h>
#include <cuda_bf16.h>
#include <cstdint>

#define NN 50000   // nodes
#define MM 10000   // hyperedges
#define EE 500000  // incidence pairs (max)
#define DD 128     // feature dim
#define NPAD 50048 // NN padded to warp multiple

// ---------------- static scratch ----------------
__device__ float g_emean[MM * DD];   // per-hyperedge mean of x    5.1 MB (fully written)
__device__ float g_eproj[MM * DD];   // emean @ Wveu               5.1 MB
__device__ float g_wvu  [DD * DD];   // W_v @ W_u_top
__device__ float g_wveu [DD * DD];   // W_v @ W_e @ W_u_bot
__device__ int   g_ecnt [MM];
__device__ int   g_ncnt [NN];
__device__ int   g_eofs [MM];
__device__ int   g_nofs [NN];
__device__ int   g_ecur [MM];
__device__ int   g_ncur [NN];
__device__ int   g_ecsr [EE];        // node ids grouped (unordered) by hyperedge
__device__ int   g_ncsr [EE];        // hyperedge ids grouped (unordered) by node
__device__ int   g_etot;
__device__ int   g_ntot;

// ---------------- zero counters ----------------
__global__ void k_zero() {
    int i = blockIdx.x * blockDim.x + threadIdx.x;
    int stride = gridDim.x * blockDim.x;
    for (int j = i; j < NN; j += stride) g_ncnt[j] = 0;
    for (int j = i; j < MM; j += stride) g_ecnt[j] = 0;
    if (i == 0) { g_etot = 0; g_ntot = 0; }
}

// ---------------- degree histograms (both directions) ----------------
__global__ void k_hist(const int* __restrict__ row, const int* __restrict__ col, int E) {
    const int tid = blockIdx.x * blockDim.x + threadIdx.x;
    const int stride = gridDim.x * blockDim.x;
    for (int e = tid; e < E; e += 2 * stride) {
        int e2 = e + stride;
        int c0 = __ldg(&col[e]);
        int r0 = __ldg(&row[e]);
        if (e2 < E) {
            int c1 = __ldg(&col[e2]);
            int r1 = __ldg(&row[e2]);
            atomicAdd(&g_ecnt[c0], 1);
            atomicAdd(&g_ecnt[c1], 1);
            atomicAdd(&g_ncnt[r0], 1);
            atomicAdd(&g_ncnt[r1], 1);
        } else {
            atomicAdd(&g_ecnt[c0], 1);
            atomicAdd(&g_ncnt[r0], 1);
        }
    }
}

// ---------------- scan-free segment offsets (warp-aggregated, both sides) ----------------
// threads [0, NPAD): node side (idx < NN active); [NPAD, ...): edge side.
// NPAD % 32 == 0 so no warp straddles the boundary.
__global__ void k_offsets() {
    int i = blockIdx.x * blockDim.x + threadIdx.x;
    int lane = threadIdx.x & 31;
    bool nodeSide = (i < NPAD);
    int idx = nodeSide ? i : (i - NPAD);
    int n = nodeSide ? NN : MM;
    int cnt = 0;
    if (idx < n) cnt = nodeSide ? g_ncnt[idx] : g_ecnt[idx];
    int s = cnt;
#pragma unroll
    for (int o = 1; o < 32; o <<= 1) {
        int t = __shfl_up_sync(0xffffffffu, s, o);
        if (lane >= o) s += t;
    }
    int warpTotal = __shfl_sync(0xffffffffu, s, 31);
    int base = 0;
    if (lane == 31) base = atomicAdd(nodeSide ? &g_ntot : &g_etot, warpTotal);
    base = __shfl_sync(0xffffffffu, base, 31);
    if (idx < n) {
        int beg = base + s - cnt;
        if (nodeSide) { g_nofs[idx] = beg; g_ncur[idx] = beg; }
        else          { g_eofs[idx] = beg; g_ecur[idx] = beg; }
    }
}

// ---------------- CSR placement (both directions in one pass) ----------------
__global__ void k_place(const int* __restrict__ row, const int* __restrict__ col, int E) {
    const int tid = blockIdx.x * blockDim.x + threadIdx.x;
    const int stride = gridDim.x * blockDim.x;
    for (int e = tid; e < E; e += stride) {
        int r = __ldg(&row[e]);
        int c = __ldg(&col[e]);
        int pn = atomicAdd(&g_ncur[r], 1);
        g_ncsr[pn] = c;
        int pe = atomicAdd(&g_ecur[c], 1);
        g_ecsr[pe] = r;
    }
}

// ---------------- weight combos: Wvu = Wv@Wu_top ; Wveu = Wv@We@Wu_bot ----------------
__global__ void __launch_bounds__(128) k_combo(
    const float* __restrict__ Wv, const float* __restrict__ We,
    const float* __restrict__ Wu)
{
    __shared__ float rowv[DD];
    __shared__ float tmp[DD];
    const int c = threadIdx.x;
    const int b = blockIdx.x;
    const float* Wu_top = Wu;
    const float* Wu_bot = Wu + DD * DD;

    if (b < DD) {
        const int r = b;
        rowv[c] = Wv[r * DD + c];
        __syncthreads();
        float a0 = 0.f, a1 = 0.f;
#pragma unroll
        for (int k = 0; k < DD; k += 2) {
            a0 = fmaf(rowv[k],     Wu_top[(k)     * DD + c], a0);
            a1 = fmaf(rowv[k + 1], Wu_top[(k + 1) * DD + c], a1);
        }
        g_wvu[r * DD + c] = a0 + a1;
    } else {
        const int r = b - DD;
        rowv[c] = Wv[r * DD + c];
        __syncthreads();
        float a0 = 0.f, a1 = 0.f;
#pragma unroll
        for (int k = 0; k < DD; k += 2) {
            a0 = fmaf(rowv[k],     We[(k)     * DD + c], a0);
            a1 = fmaf(rowv[k + 1], We[(k + 1) * DD + c], a1);
        }
        tmp[c] = a0 + a1;
        __syncthreads();
        float b0 = 0.f, b1 = 0.f;
#pragma unroll
        for (int k = 0; k < DD; k += 2) {
            b0 = fmaf(tmp[k],     Wu_bot[(k)     * DD + c], b0);
            b1 = fmaf(tmp[k + 1], Wu_bot[(k + 1) * DD + c], b1);
        }
        g_wveu[r * DD + c] = b0 + b1;
    }
}

// ---------------- L2-only vector load ----------------
__device__ __forceinline__ float4 ldcg_v4(const float* p) {
    float4 v;
    asm volatile("ld.global.cg.v4.f32 {%0,%1,%2,%3}, [%4];"
                 : "=f"(v.x), "=f"(v.y), "=f"(v.z), "=f"(v.w) : "l"(p));
    return v;
}

// ---------------- gather_e: per-hyperedge mean of raw x ----------------
__global__ void k_gather_e(const float* __restrict__ x) {
    const int lane = threadIdx.x & 31;
    const int seg = (blockIdx.x * blockDim.x + threadIdx.x) >> 5;
    if (seg >= MM) return;
    const int beg = g_eofs[seg];
    const int cnt = g_ecnt[seg];
    const int end = beg + cnt;
    float4 acc = make_float4(0.f, 0.f, 0.f, 0.f);
    int i = beg;
    for (; i + 1 < end; i += 2) {
        int r0 = __ldg(&g_ecsr[i]);
        int r1 = __ldg(&g_ecsr[i + 1]);
        float4 v0 = ldcg_v4(&x[(size_t)r0 * DD + lane * 4]);
        float4 v1 = ldcg_v4(&x[(size_t)r1 * DD + lane * 4]);
        acc.x += v0.x + v1.x; acc.y += v0.y + v1.y;
        acc.z += v0.z + v1.z; acc.w += v0.w + v1.w;
    }
    if (i < end) {
        int r0 = __ldg(&g_ecsr[i]);
        float4 v0 = ldcg_v4(&x[(size_t)r0 * DD + lane * 4]);
        acc.x += v0.x; acc.y += v0.y; acc.z += v0.z; acc.w += v0.w;
    }
    float inv = 1.0f / fmaxf((float)cnt, 1.0f);
    acc.x *= inv; acc.y *= inv; acc.z *= inv; acc.w *= inv;
    *(float4*)&g_emean[(size_t)seg * DD + lane * 4] = acc;
}

// ---------------- gather_n: per-node mean of eproj + fused relu epilogue ----------------
__global__ void k_gather_n(float* __restrict__ out, int N) {
    const int lane = threadIdx.x & 31;
    const int seg = (blockIdx.x * blockDim.x + threadIdx.x) >> 5;
    if (seg >= N) return;
    const int beg = g_nofs[seg];
    const int cnt = g_ncnt[seg];
    const int end = beg + cnt;
    float4 acc = make_float4(0.f, 0.f, 0.f, 0.f);
    int i = beg;
    for (; i + 1 < end; i += 2) {
        int c0 = __ldg(&g_ncsr[i]);
        int c1 = __ldg(&g_ncsr[i + 1]);
        float4 v0 = ldcg_v4(&g_eproj[(size_t)c0 * DD + lane * 4]);
        float4 v1 = ldcg_v4(&g_eproj[(size_t)c1 * DD + lane * 4]);
        acc.x += v0.x + v1.x; acc.y += v0.y + v1.y;
        acc.z += v0.z + v1.z; acc.w += v0.w + v1.w;
    }
    if (i < end) {
        int c0 = __ldg(&g_ncsr[i]);
        float4 v0 = ldcg_v4(&g_eproj[(size_t)c0 * DD + lane * 4]);
        acc.x += v0.x; acc.y += v0.y; acc.z += v0.z; acc.w += v0.w;
    }
    float inv = 1.0f / fmaxf((float)cnt, 1.0f);
    float4 o = *(const float4*)&out[(size_t)seg * DD + lane * 4];
    o.x = fmaxf(fmaf(acc.x, inv, o.x), 0.0f);
    o.y = fmaxf(fmaf(acc.y, inv, o.y), 0.0f);
    o.z = fmaxf(fmaf(acc.z, inv, o.z), 0.0f);
    o.w = fmaxf(fmaf(acc.w, inv, o.w), 0.0f);
    *(float4*)&out[(size_t)seg * DD + lane * 4] = o;
}

// ---------------- packed f32x2 FMA helpers ----------------
__device__ __forceinline__ unsigned long long pack_dup(float a) {
    unsigned long long r;
    uint32_t u = __float_as_uint(a);
    asm("mov.b64 %0, {%1, %1};" : "=l"(r) : "r"(u));
    return r;
}
__device__ __forceinline__ void fma_x2(unsigned long long& acc,
                                       unsigned long long a, unsigned long long b) {
    asm("fma.rn.f32x2 %0, %1, %2, %0;" : "+l"(acc) : "l"(a), "l"(b));
}
__device__ __forceinline__ float2 unpack_x2(unsigned long long v) {
    float2 r;
    uint32_t lo, hi;
    asm("mov.b64 {%0, %1}, %2;" : "=r"(lo), "=r"(hi) : "l"(v));
    r.x = __uint_as_float(lo);
    r.y = __uint_as_float(hi);
    return r;
}

// ---------------- double-buffered SGEMM body (f32x2 inner loop) ----------------
template <bool BIAS>
__device__ __forceinline__ void gemm_body(
    const float* __restrict__ A0, const float* __restrict__ Bm,
    const float* __restrict__ bias, float* __restrict__ C, int Mrows)
{
    __shared__ float As[2][16][132];
    __shared__ __align__(16) float Bs[2][16][128];

    const int tid = threadIdx.x;
    const int ty = tid >> 4;
    const int tx = tid & 15;
    const int rowBase = blockIdx.x * 128;

    const int aRow = tid >> 2;
    const int aCol = (tid & 3) << 2;
    const int bRow = tid >> 5;
    const int bCol = (tid & 31) << 2;

    unsigned long long acc2[8][4];
#pragma unroll
    for (int i = 0; i < 8; i++)
#pragma unroll
        for (int j = 0; j < 4; j++) acc2[i][j] = 0ull;

    float4 pa[2], pb[2];
#pragma unroll
    for (int p = 0; p < 2; p++) {
        int gr = rowBase + aRow + p * 64;
        pa[p] = make_float4(0.f, 0.f, 0.f, 0.f);
        if (gr < Mrows) pa[p] = *(const float4*)&A0[(size_t)gr * DD + aCol];
        pb[p] = *(const float4*)&Bm[(size_t)(bRow + p * 8) * DD + bCol];
    }
#pragma unroll
    for (int p = 0; p < 2; p++) {
        int r = aRow + p * 64;
        As[0][aCol + 0][r] = pa[p].x;
        As[0][aCol + 1][r] = pa[p].y;
        As[0][aCol + 2][r] = pa[p].z;
        As[0][aCol + 3][r] = pa[p].w;
        *(float4*)&Bs[0][bRow + p * 8][bCol] = pb[p];
    }
    __syncthreads();

#pragma unroll
    for (int kb = 0; kb < 8; kb++) {
        if (kb < 7) {
            const int ko = (kb + 1) * 16;
#pragma unroll
            for (int p = 0; p < 2; p++) {
                int gr = rowBase + aRow + p * 64;
                pa[p] = make_float4(0.f, 0.f, 0.f, 0.f);
                if (gr < Mrows) pa[p] = *(const float4*)&A0[(size_t)gr * DD + ko + aCol];
                pb[p] = *(const float4*)&Bm[(size_t)(ko + bRow + p * 8) * DD + bCol];
            }
        }
        const int cb = kb & 1;
#pragma unroll
        for (int k = 0; k < 16; k++) {
            float ar[8];
            *(float4*)&ar[0] = *(const float4*)&As[cb][k][ty * 8];
            *(float4*)&ar[4] = *(const float4*)&As[cb][k][ty * 8 + 4];
            const unsigned long long* bp =
                (const unsigned long long*)&Bs[cb][k][tx * 8];
            unsigned long long br2[4];
            br2[0] = bp[0]; br2[1] = bp[1]; br2[2] = bp[2]; br2[3] = bp[3];
#pragma unroll
            for (int i = 0; i < 8; i++) {
                unsigned long long ai = pack_dup(ar[i]);
#pragma unroll
                for (int j = 0; j < 4; j++) fma_x2(acc2[i][j], ai, br2[j]);
            }
        }
        if (kb < 7) {
            const int nb = cb ^ 1;
#pragma unroll
            for (int p = 0; p < 2; p++) {
                int r = aRow + p * 64;
                As[nb][aCol + 0][r] = pa[p].x;
                As[nb][aCol + 1][r] = pa[p].y;
                As[nb][aCol + 2][r] = pa[p].z;
                As[nb][aCol + 3][r] = pa[p].w;
                *(float4*)&Bs[nb][bRow + p * 8][bCol] = pb[p];
            }
            __syncthreads();
        }
    }

#pragma unroll
    for (int i = 0; i < 8; i++) {
        int gr = rowBase + ty * 8 + i;
        if (gr >= Mrows) continue;
#pragma unroll
        for (int j = 0; j < 4; j += 2) {
            float2 v0 = unpack_x2(acc2[i][j]);
            float2 v1 = unpack_x2(acc2[i][j + 1]);
            float4 v = make_float4(v0.x, v0.y, v1.x, v1.y);
            int gc = tx * 8 + j * 2;
            if (BIAS) {
                v.x += __ldg(&bias[gc + 0]);
                v.y += __ldg(&bias[gc + 1]);
                v.z += __ldg(&bias[gc + 2]);
                v.w += __ldg(&bias[gc + 3]);
            }
            *(float4*)&C[(size_t)gr * DD + gc] = v;
        }
    }
}

__global__ void __launch_bounds__(256, 2) k_gemm_bias(
    const float* A, const float* B, const float* bias, float* C, int Mrows)
{
    gemm_body<true>(A, B, bias, C, Mrows);
}

__global__ void __launch_bounds__(256, 2) k_gemm_plain(
    const float* A, const float* B, float* C, int Mrows)
{
    gemm_body<false>(A, B, nullptr, C, Mrows);
}

// ---------------- launch ----------------
extern "C" void kernel_launch(void* const* d_in, const int* in_sizes, int n_in,
                              void* d_out, int out_size)
{
    const float* x   = (const float*)d_in[0];
    const int*   ei  = (const int*)  d_in[1];
    const float* Wv  = (const float*)d_in[2];
    const float* We  = (const float*)d_in[3];
    const float* Wu  = (const float*)d_in[4];
    const float* bu  = (const float*)d_in[5];
    float* out = (float*)d_out;

    const int E = in_sizes[1] / 2;
    const int N = in_sizes[0] / DD;
    const int* rowp = ei;
    const int* colp = ei + E;

    float* emean; cudaGetSymbolAddress((void**)&emean, g_emean);
    float* eproj; cudaGetSymbolAddress((void**)&eproj, g_eproj);
    float* wvu;   cudaGetSymbolAddress((void**)&wvu,   g_wvu);
    float* wveu;  cudaGetSymbolAddress((void**)&wveu,  g_wveu);

    cudaStream_t side1;
    cudaStreamCreateWithFlags(&side1, cudaStreamNonBlocking);
    cudaEvent_t evEntry, evGemm;
    cudaEventCreateWithFlags(&evEntry, cudaEventDisableTiming);
    cudaEventCreateWithFlags(&evGemm,  cudaEventDisableTiming);

    // side1 (forks at entry): combo -> out = x@Wvu + bias (plain stores)
    cudaEventRecord(evEntry, 0);
    cudaStreamWaitEvent(side1, evEntry, 0);
    k_combo<<<256, 128, 0, side1>>>(Wv, We, Wu);
    k_gemm_bias<<<(N + 127) / 128, 256, 0, side1>>>(x, wvu, bu, out, N);
    cudaEventRecord(evGemm, side1);

    // main: CSR build -> gather_e -> gemm -> gather_n
    k_zero<<<64, 256>>>();
    k_hist<<<4096, 256>>>(rowp, colp, E);
    k_offsets<<<(NPAD + 10240 + 255) / 256, 256>>>();
    k_place<<<2048, 256>>>(rowp, colp, E);
    k_gather_e<<<(MM * 32 + 255) / 256, 256>>>(x);
    k_gemm_plain<<<(MM + 127) / 128, 256>>>(emean, wveu, eproj, MM);

    // join side GEMM, then fused gather + relu epilogue
    cudaStreamWaitEvent(0, evGemm, 0);
    k_gather_n<<<(N * 32 + 255) / 256, 256>>>(out, N);

    cudaEventDestroy(evEntry);
    cudaEventDestroy(evGemm);
    cudaStreamDestroy(side1);
}